// round 7
// baseline (speedup 1.0000x reference)
#include <cuda_runtime.h>
#include <cuda_bf16.h>
#include <math.h>

// ---------------------------------------------------------------------------
// ELMo embeddings, fp32 end-to-end.
// Pipeline: embed -> per layer { init h/c, xW GEMM (both dirs), 96x (stepA
// (z=xW+h@Wr, gates, c, a=o*tanh(c)), stepB (h=clip(a@Wp), emit)) } -> stats
// -> weighted output. All scratch in __device__ globals; plain launches only.
// ---------------------------------------------------------------------------

namespace {
constexpr int Bn = 8;     // batch
constexpr int Tn = 96;    // time
constexpr int En = 256;   // embed dim
constexpr int Hn = 2048;  // hidden
constexpr int Pn = 256;   // projection
constexpr int Gn = 8192;  // 4*H (gate concat)
}

// scratch (device globals; allocation-free)
__device__ float g_emb[Bn * Tn * En];          // token embeddings
__device__ float g_y0[2][Bn * Tn * Pn];        // layer-0 outputs per dir
__device__ float g_y1[2][Bn * Tn * Pn];        // layer-1 outputs per dir
__device__ float g_xW[2][(size_t)Tn * Bn * Gn]; // x@Wk+b per dir, step-major (50 MB)
__device__ float g_h[2][Bn * Pn];              // recurrent h per dir
__device__ float g_c[2][Bn * Hn];              // recurrent c per dir
__device__ float g_a[2][Bn * Hn];              // o*tanh(c) staging per step
__device__ float g_mean[3][Bn];
__device__ float g_var[3][Bn];

// ---------------------------------------------------------------------------
__global__ void k_embed(const int* __restrict__ tok, const float* __restrict__ tab) {
    int i = blockIdx.x * 256 + threadIdx.x;       // over B*T*E = 196608
    int bt = i >> 8;
    int e = i & 255;
    g_emb[i] = tab[(size_t)tok[bt] * En + e];
}

__global__ void k_init() {
    int i = blockIdx.x * 256 + threadIdx.x;       // grid covers 2*B*H = 32768
    if (i < 2 * Bn * Pn) (&g_h[0][0])[i] = 0.f;
    (&g_c[0][0])[i] = 0.f;
}

// ---------------------------------------------------------------------------
// xW GEMM: out[d][s*8+b][n] = x_d[b][t(s)][:] . Wk[d*2+layer][:,n] + bias[n]
// M=768 (s,b), N=8192, K=256. Tile BM=128 BN=64 BK=32, 256 thr, 8x4 microtile.
// ---------------------------------------------------------------------------
__global__ void k_xw(const float* __restrict__ Wk, const float* __restrict__ bias,
                     int layer) {
    const int d = blockIdx.z;
    const int widx = d * 2 + layer;
    const float* __restrict__ x = (layer == 0) ? g_emb : g_y0[d];
    const float* __restrict__ W = Wk + (size_t)widx * En * Gn;
    const float* __restrict__ bi = bias + (size_t)widx * Gn;
    float* __restrict__ out = g_xW[d];
    const int n0 = blockIdx.x * 64;
    const int m0 = blockIdx.y * 128;
    const bool rev = (d == 1);
    const int tid = threadIdx.x;
    const int tx = tid & 15;      // -> 4 n cols
    const int ty = tid >> 4;      // -> 8 m rows

    __shared__ float As[32][129]; // [k][m], pad 129 for conflict-free staging
    __shared__ float Bs[32][64];  // [k][n]

    float acc[8][4];
#pragma unroll
    for (int i = 0; i < 8; ++i) acc[i][0] = acc[i][1] = acc[i][2] = acc[i][3] = 0.f;

    // A loader: thread -> (row ml, 16 consecutive k at kl)
    const int ml = tid >> 1;
    const int kl = (tid & 1) * 16;
    const int m = m0 + ml;
    const int sA = m >> 3, bA = m & 7;
    const int tA = rev ? (Tn - 1 - sA) : sA;
    const float* xrow = x + (size_t)(bA * Tn + tA) * En;

    // B loader: thread -> (k row kb, 8 consecutive n at nb)
    const int kb = tid >> 3;
    const int nb = (tid & 7) * 8;

    for (int k0 = 0; k0 < En; k0 += 32) {
#pragma unroll
        for (int j4 = 0; j4 < 16; j4 += 4) {
            float4 v = *(const float4*)(xrow + k0 + kl + j4);
            As[kl + j4 + 0][ml] = v.x;
            As[kl + j4 + 1][ml] = v.y;
            As[kl + j4 + 2][ml] = v.z;
            As[kl + j4 + 3][ml] = v.w;
        }
        {
            const float* wr = W + (size_t)(k0 + kb) * Gn + n0 + nb;
            float4 v0 = *(const float4*)(wr);
            float4 v1 = *(const float4*)(wr + 4);
            *(float4*)(&Bs[kb][nb]) = v0;
            *(float4*)(&Bs[kb][nb + 4]) = v1;
        }
        __syncthreads();
#pragma unroll
        for (int k = 0; k < 32; ++k) {
            float4 bfr = *(const float4*)(&Bs[k][tx * 4]);
#pragma unroll
            for (int i = 0; i < 8; ++i) {
                float a = As[k][ty * 8 + i];
                acc[i][0] += a * bfr.x;
                acc[i][1] += a * bfr.y;
                acc[i][2] += a * bfr.z;
                acc[i][3] += a * bfr.w;
            }
        }
        __syncthreads();
    }
    float4 bv = *(const float4*)(bi + n0 + tx * 4);
#pragma unroll
    for (int i = 0; i < 8; ++i) {
        int mm = m0 + ty * 8 + i;
        float4 r = make_float4(acc[i][0] + bv.x, acc[i][1] + bv.y,
                               acc[i][2] + bv.z, acc[i][3] + bv.w);
        *(float4*)(out + (size_t)mm * Gn + n0 + tx * 4) = r;
    }
}

// ---------------------------------------------------------------------------
// stepA: per (dir, 32 hidden units): z = xW[s] + h@Wr ; gates ; c update ;
//        a = o*tanh(c_new).  grid (64, 2), 256 threads.
// Thread (kc=warp 0..7 = K chunk, cg 0..31 = 4 consecutive gate-cols).
// Local col lc = cg*4+cv in [0,128): gate = lc>>5, unit u = lc&31.
// ---------------------------------------------------------------------------
__global__ void k_stepA(const float* __restrict__ Wr, const float* __restrict__ mask,
                        int layer, int s) {
    const int d = blockIdx.y;
    const int widx = d * 2 + layer;
    const int U0 = blockIdx.x * 32;
    const float* __restrict__ W = Wr + (size_t)widx * Pn * Gn;
    const int tid = threadIdx.x;
    const int kc = tid >> 5;
    const int cg = tid & 31;

    __shared__ float h_sm[Bn][En];            // 8 KB
    __shared__ float part[8][4][Bn][32];      // 32 KB: [kc][cv][b][cg]

    {
        const float* hp = g_h[d];
#pragma unroll
        for (int i = tid; i < Bn * Pn; i += 256) h_sm[i >> 8][i & 255] = hp[i];
    }
    __syncthreads();

    float acc[4][8];
#pragma unroll
    for (int cv = 0; cv < 4; ++cv)
#pragma unroll
        for (int b = 0; b < 8; ++b) acc[cv][b] = 0.f;

    const int gate = cg >> 3;
    const int goff = (cg & 7) * 4;
    const float* wp = W + (size_t)(gate * Hn + U0 + goff);
    const int k0 = kc * 32;
#pragma unroll 4
    for (int k = k0; k < k0 + 32; ++k) {
        float4 w4 = *(const float4*)(wp + (size_t)k * Gn);
#pragma unroll
        for (int b = 0; b < 8; ++b) {
            float hv = h_sm[b][k];
            acc[0][b] += w4.x * hv;
            acc[1][b] += w4.y * hv;
            acc[2][b] += w4.z * hv;
            acc[3][b] += w4.w * hv;
        }
    }
#pragma unroll
    for (int cv = 0; cv < 4; ++cv)
#pragma unroll
        for (int b = 0; b < 8; ++b) part[kc][cv][b][cg] = acc[cv][b];
    __syncthreads();

    // reduce K partials + add xW (thread -> (rb, 4 cols at rcg*4))
    const int rb = tid >> 5;
    const int rcg = tid & 31;
    const int rgate = rcg >> 3;
    const int rgoff = (rcg & 7) * 4;
    const float* xwp = g_xW[d] + (size_t)(s * Bn + rb) * Gn + rgate * Hn + U0 + rgoff;
    float4 z4 = *(const float4*)xwp;
    float z0 = z4.x, z1 = z4.y, z2 = z4.z, z3 = z4.w;
#pragma unroll
    for (int kk = 0; kk < 8; ++kk) {
        z0 += part[kk][0][rb][rcg];
        z1 += part[kk][1][rb][rcg];
        z2 += part[kk][2][rb][rcg];
        z3 += part[kk][3][rb][rcg];
    }
    __syncthreads();
    float* z_sm = &part[0][0][0][0];          // reuse: z_sm[b*128 + lc]
    *(float4*)(z_sm + rb * 128 + rcg * 4) = make_float4(z0, z1, z2, z3);
    __syncthreads();

    // gates: thread -> (b, u)
    const int b = tid >> 5;
    const int u = tid & 31;
    float zi = z_sm[b * 128 + u];
    float zf = z_sm[b * 128 + 32 + u];
    float zg = z_sm[b * 128 + 64 + u];
    float zo = z_sm[b * 128 + 96 + u];
    float ig = 1.f / (1.f + expf(-zi));
    float fg = 1.f / (1.f + expf(-zf));
    float gg = tanhf(zg);
    float og = 1.f / (1.f + expf(-zo));
    const int t = (d == 1) ? (Tn - 1 - s) : s;
    const float mt = mask[b * Tn + t];
    const size_t cidx = (size_t)b * Hn + U0 + u;
    float cold = g_c[d][cidx];
    float cn = fminf(3.f, fmaxf(-3.f, fg * cold + ig * gg));
    g_c[d][cidx] = (mt > 0.f) ? cn : cold;
    g_a[d][cidx] = og * tanhf(cn);
}

// ---------------------------------------------------------------------------
// stepB: h_new = clip(a @ Wp, +-3) with mask keep; write h and y[t].
// grid (4 p-chunks, 8 batch, 2 dir), 128 threads; K split 8x256.
// ---------------------------------------------------------------------------
__global__ void k_stepB(const float* __restrict__ Wp, const float* __restrict__ mask,
                        int layer, int s) {
    const int d = blockIdx.z;
    const int b = blockIdx.y;
    const int pc = blockIdx.x;
    const int widx = d * 2 + layer;
    const float* __restrict__ W = Wp + (size_t)widx * Hn * Pn;

    __shared__ float a_sm[Hn];  // 8 KB
    __shared__ float pb[8][64];
    {
        const float* ap = g_a[d] + (size_t)b * Hn;
        for (int i = threadIdx.x; i < Hn; i += 128) a_sm[i] = ap[i];
    }
    __syncthreads();

    const int kc = threadIdx.x >> 4;  // 0..7
    const int pq = threadIdx.x & 15;  // 4 p each
    const int p0 = pc * 64 + pq * 4;
    float a0 = 0.f, a1 = 0.f, a2 = 0.f, a3 = 0.f;
    const int ks = kc * 256;
#pragma unroll 4
    for (int k = ks; k < ks + 256; ++k) {
        float av = a_sm[k];
        float4 w4 = *(const float4*)(W + (size_t)k * Pn + p0);
        a0 += av * w4.x;
        a1 += av * w4.y;
        a2 += av * w4.z;
        a3 += av * w4.w;
    }
    *(float4*)(&pb[kc][pq * 4]) = make_float4(a0, a1, a2, a3);
    __syncthreads();

    if (threadIdx.x < 64) {
        const int p = threadIdx.x;
        float hn = 0.f;
#pragma unroll
        for (int kk = 0; kk < 8; ++kk) hn += pb[kk][p];
        hn = fminf(3.f, fmaxf(-3.f, hn));
        const int t = (d == 1) ? (Tn - 1 - s) : s;
        const float mt = mask[b * Tn + t];
        const size_t hidx = (size_t)b * Pn + pc * 64 + p;
        float hv = (mt > 0.f) ? hn : g_h[d][hidx];
        g_h[d][hidx] = hv;
        float* y = (layer == 0) ? g_y0[d] : g_y1[d];
        y[((size_t)b * Tn + t) * Pn + pc * 64 + p] = hv;
    }
}

// ---------------------------------------------------------------------------
// Epilogue
// ---------------------------------------------------------------------------
__device__ __forceinline__ float layer_val(int l, int b, int t, int ch) {
    if (l == 0) return g_emb[(size_t)(b * Tn + t) * En + (ch & 255)];
    const int dd = ch >> 8;
    const size_t idx = (size_t)(b * Tn + t) * Pn + (ch & 255);
    float v = g_y0[dd][idx];
    if (l == 2) v += g_y1[dd][idx];
    return v;
}

__global__ void k_stats(const float* __restrict__ mask) {
    const int b = blockIdx.x;
    const int l = blockIdx.y;
    __shared__ float red[256];
    const int tid = threadIdx.x;

    float nm = 0.f;
    for (int t = tid; t < Tn; t += 256) nm += mask[b * Tn + t];
    red[tid] = nm;
    __syncthreads();
    for (int st = 128; st > 0; st >>= 1) {
        if (tid < st) red[tid] += red[tid + st];
        __syncthreads();
    }
    const float num = red[0];
    __syncthreads();

    float sm = 0.f;
    for (int i = tid; i < Tn * 512; i += 256) {
        int t = i >> 9, ch = i & 511;
        sm += layer_val(l, b, t, ch) * mask[b * Tn + t];
    }
    red[tid] = sm;
    __syncthreads();
    for (int st = 128; st > 0; st >>= 1) {
        if (tid < st) red[tid] += red[tid + st];
        __syncthreads();
    }
    const float mean = red[0] / num;
    __syncthreads();

    float vs = 0.f;
    for (int i = tid; i < Tn * 512; i += 256) {
        int t = i >> 9, ch = i & 511;
        float m = mask[b * Tn + t];
        float dd = (layer_val(l, b, t, ch) * m - mean) * m;
        vs += dd * dd;
    }
    red[tid] = vs;
    __syncthreads();
    for (int st = 128; st > 0; st >>= 1) {
        if (tid < st) red[tid] += red[tid + st];
        __syncthreads();
    }
    if (tid == 0) {
        g_mean[l][b] = mean;
        g_var[l][b] = red[0] / num;
    }
}

__global__ void k_final(const float* __restrict__ elmo_w, const float* __restrict__ gamma,
                        float* __restrict__ out) {
    const int i = blockIdx.x * 256 + threadIdx.x;  // over B*T*512 = 393216
    const int ch = i & 511;
    const int bt = i >> 9;
    const int b = bt / Tn;
    const int t = bt - b * Tn;
    float w0 = elmo_w[0], w1 = elmo_w[1], w2 = elmo_w[2];
    float mx = fmaxf(w0, fmaxf(w1, w2));
    float e0 = expf(w0 - mx), e1 = expf(w1 - mx), e2 = expf(w2 - mx);
    float inv = 1.f / (e0 + e1 + e2);
    float gm = gamma[0];
    float r = 0.f;
    r += e0 * inv * (layer_val(0, b, t, ch) - g_mean[0][b]) / sqrtf(g_var[0][b] + 1e-12f);
    r += e1 * inv * (layer_val(1, b, t, ch) - g_mean[1][b]) / sqrtf(g_var[1][b] + 1e-12f);
    r += e2 * inv * (layer_val(2, b, t, ch) - g_mean[2][b]) / sqrtf(g_var[2][b] + 1e-12f);
    out[i] = gm * r;
}

// ---------------------------------------------------------------------------
extern "C" void kernel_launch(void* const* d_in, const int* in_sizes, int n_in,
                              void* d_out, int out_size) {
    (void)in_sizes; (void)n_in; (void)out_size;
    const int*   tokens = (const int*)d_in[0];
    const float* mask   = (const float*)d_in[1];
    const float* table  = (const float*)d_in[2];
    const float* Wk     = (const float*)d_in[3];
    const float* Wr     = (const float*)d_in[4];
    const float* bias   = (const float*)d_in[5];
    const float* Wp     = (const float*)d_in[6];
    const float* elmo_w = (const float*)d_in[7];
    const float* gamma  = (const float*)d_in[8];
    float* out = (float*)d_out;

    k_embed<<<768, 256>>>(tokens, table);
    for (int layer = 0; layer < 2; ++layer) {
        k_init<<<128, 256>>>();
        k_xw<<<dim3(Gn / 64, (Tn * Bn) / 128, 2), 256>>>(Wk, bias, layer);
        for (int s = 0; s < Tn; ++s) {
            k_stepA<<<dim3(64, 2), 256>>>(Wr, mask, layer, s);
            k_stepB<<<dim3(4, 8, 2), 128>>>(Wp, mask, layer, s);
        }
    }
    k_stats<<<dim3(8, 3), 256>>>(mask);
    k_final<<<1536, 256>>>(elmo_w, gamma, out);
}

// round 8
// speedup vs baseline: 1.5968x; 1.5968x over previous
#include <cuda_runtime.h>
#include <cuda_bf16.h>
#include <math.h>

// ---------------------------------------------------------------------------
// ELMo embeddings, fp32. Persistent-recurrence version:
//   embed -> per layer { xW GEMM ; persistent LSTM kernel (weights in SMEM,
//   lock-step grid barrier per phase) } -> stats -> weighted output.
// ---------------------------------------------------------------------------

namespace {
constexpr int Bn = 8;     // batch
constexpr int Tn = 96;    // time
constexpr int En = 256;   // embed dim
constexpr int Hn = 2048;  // hidden
constexpr int Pn = 256;   // projection
constexpr int Gn = 8192;  // 4*H
constexpr int NBLK = 128; // persistent grid size (2 dirs x 64)
}

// scratch (device globals; allocation-free)
__device__ float g_emb[Bn * Tn * En];
__device__ float g_y0[2][Bn * Tn * Pn];
__device__ float g_y1[2][Bn * Tn * Pn];
__device__ float g_xW[2][(size_t)Tn * Bn * Gn];  // x@Wk+b, step-major
__device__ float g_h[2][Bn * Pn];
__device__ float g_a[2][Bn * Hn];
__device__ float g_mean[3][Bn];
__device__ float g_var[3][Bn];

// grid-barrier state (monotonic generations; never reset -> replay-safe)
__device__ unsigned g_slots[NBLK];
__device__ unsigned g_epoch;

// ---------------------------------------------------------------------------
__global__ void k_embed(const int* __restrict__ tok, const float* __restrict__ tab) {
    int i = blockIdx.x * 256 + threadIdx.x;  // B*T*E = 196608
    int bt = i >> 8;
    int e = i & 255;
    g_emb[i] = tab[(size_t)tok[bt] * En + e];
}

// ---------------------------------------------------------------------------
// xW GEMM (unchanged from R7-passing version).
// ---------------------------------------------------------------------------
__global__ void k_xw(const float* __restrict__ Wk, const float* __restrict__ bias,
                     int layer) {
    const int d = blockIdx.z;
    const int widx = d * 2 + layer;
    const float* __restrict__ x = (layer == 0) ? g_emb : g_y0[d];
    const float* __restrict__ W = Wk + (size_t)widx * En * Gn;
    const float* __restrict__ bi = bias + (size_t)widx * Gn;
    float* __restrict__ out = g_xW[d];
    const int n0 = blockIdx.x * 64;
    const int m0 = blockIdx.y * 128;
    const bool rev = (d == 1);
    const int tid = threadIdx.x;
    const int tx = tid & 15;
    const int ty = tid >> 4;

    __shared__ float As[32][129];
    __shared__ float Bs[32][64];

    float acc[8][4];
#pragma unroll
    for (int i = 0; i < 8; ++i) acc[i][0] = acc[i][1] = acc[i][2] = acc[i][3] = 0.f;

    const int ml = tid >> 1;
    const int kl = (tid & 1) * 16;
    const int m = m0 + ml;
    const int sA = m >> 3, bA = m & 7;
    const int tA = rev ? (Tn - 1 - sA) : sA;
    const float* xrow = x + (size_t)(bA * Tn + tA) * En;

    const int kb = tid >> 3;
    const int nb = (tid & 7) * 8;

    for (int k0 = 0; k0 < En; k0 += 32) {
#pragma unroll
        for (int j4 = 0; j4 < 16; j4 += 4) {
            float4 v = *(const float4*)(xrow + k0 + kl + j4);
            As[kl + j4 + 0][ml] = v.x;
            As[kl + j4 + 1][ml] = v.y;
            As[kl + j4 + 2][ml] = v.z;
            As[kl + j4 + 3][ml] = v.w;
        }
        {
            const float* wr = W + (size_t)(k0 + kb) * Gn + n0 + nb;
            float4 v0 = *(const float4*)(wr);
            float4 v1 = *(const float4*)(wr + 4);
            *(float4*)(&Bs[kb][nb]) = v0;
            *(float4*)(&Bs[kb][nb + 4]) = v1;
        }
        __syncthreads();
#pragma unroll
        for (int k = 0; k < 32; ++k) {
            float4 bfr = *(const float4*)(&Bs[k][tx * 4]);
#pragma unroll
            for (int i = 0; i < 8; ++i) {
                float a = As[k][ty * 8 + i];
                acc[i][0] += a * bfr.x;
                acc[i][1] += a * bfr.y;
                acc[i][2] += a * bfr.z;
                acc[i][3] += a * bfr.w;
            }
        }
        __syncthreads();
    }
    float4 bv = *(const float4*)(bi + n0 + tx * 4);
#pragma unroll
    for (int i = 0; i < 8; ++i) {
        int mm = m0 + ty * 8 + i;
        float4 r = make_float4(acc[i][0] + bv.x, acc[i][1] + bv.y,
                               acc[i][2] + bv.z, acc[i][3] + bv.w);
        *(float4*)(out + (size_t)mm * Gn + n0 + tx * 4) = r;
    }
}

// ---------------------------------------------------------------------------
// Persistent LSTM recurrence. 128 blocks x 512 threads, 1 block/SM.
// Block bx: dir d = bx>>6, slice q = bx&63 -> units U0=q*32, proj cols P0=q*4.
// SMEM: Wr slice [256][128] 128KB, Wp slice [4][2048] 32KB, h 8KB, zpart 8KB,
//       z 4KB, c 1KB, red 256B  => 185600 B dynamic.
// Per step: phase1 (z=xW+h@Wr, gates, c, a) | barrier | phase2 (h=clip(a@Wp))
//           | barrier.
// ---------------------------------------------------------------------------
__device__ __forceinline__ float fsig(float x) {
    return __fdividef(1.f, 1.f + __expf(-x));
}
__device__ __forceinline__ float ftanh(float x) {
    return __fdividef(2.f, 1.f + __expf(-2.f * x)) - 1.f;
}

__device__ __forceinline__ void grid_barrier(unsigned gen, int tid, int bx) {
    __syncthreads();
    if (tid == 0) {
        __threadfence();
        *((volatile unsigned*)&g_slots[bx]) = gen;
    }
    if (tid < NBLK) {
        while ((int)(*((volatile unsigned*)&g_slots[tid]) - gen) < 0) {}
    }
    __threadfence();
    __syncthreads();
}

__global__ void __launch_bounds__(512, 1)
k_recur(const float* __restrict__ Wr, const float* __restrict__ Wp,
        const float* __restrict__ mask, int layer) {
    extern __shared__ float sm[];
    float* Wr_sm = sm;               // [256][128]  (col lc = gate*32+u)
    float* Wp_sm = sm + 32768;       // [4][2048]   (Wp_sm[p][k])
    float* h_sm  = sm + 40960;       // [8][256]
    float* zpart = sm + 43008;       // [2][8][128]
    float* z_sm  = sm + 45056;       // [8][128]
    float* c_sm  = sm + 46080;       // [8][32]
    float* red   = sm + 46336;       // [8][2][4]

    const int tid = threadIdx.x;
    const int bx = blockIdx.x;
    const int d = bx >> 6;
    const int q = bx & 63;
    const int U0 = q * 32;
    const int P0 = q * 4;
    const int widx = d * 2 + layer;

    // ---- preload weights ----
    {
        const float* Wg = Wr + (size_t)widx * Pn * Gn;
        for (int i = tid; i < 256 * 128; i += 512) {
            int k = i >> 7, lc = i & 127;
            int gate = lc >> 5, u = lc & 31;
            Wr_sm[i] = __ldg(&Wg[(size_t)k * Gn + gate * Hn + U0 + u]);
        }
        const float* Wpg = Wp + (size_t)widx * Hn * Pn;
        for (int k = tid; k < Hn; k += 512) {
            float4 v = __ldg((const float4*)&Wpg[(size_t)k * Pn + P0]);
            Wp_sm[k] = v.x;
            Wp_sm[2048 + k] = v.y;
            Wp_sm[4096 + k] = v.z;
            Wp_sm[6144 + k] = v.w;
        }
    }
    if (tid < 256) c_sm[tid] = 0.f;

    const unsigned base = *((volatile unsigned*)&g_epoch);
    unsigned gen = base;
    float h_own = 0.f;  // tid<32: this thread's (b,p) h value
    float* __restrict__ yb = (layer == 0) ? g_y0[d] : g_y1[d];
    float* __restrict__ hg = g_h[d];
    float* __restrict__ ag = g_a[d];
    const float* __restrict__ xWd = g_xW[d];
    __syncthreads();

    // thread mappings
    const int kh = tid >> 8;          // z: k half
    const int zb = (tid >> 5) & 7;    // z: batch
    const int c4 = tid & 31;          // z: 4-col group
    const int w = tid >> 5;           // phase2 warp
    const int lane = tid & 31;
    const int pb = w >> 1;            // phase2 batch
    const int half = w & 1;           // phase2 k half

    for (int s = 0; s < Tn; ++s) {
        const int t = d ? (Tn - 1 - s) : s;

        // ---- stage h ----
        if (s == 0) {
            for (int i = tid; i < Bn * Pn; i += 512) h_sm[i] = 0.f;
        } else {
            ((float4*)h_sm)[tid] = __ldcg(((const float4*)hg) + tid);
        }
        __syncthreads();

        // ---- phase 1: z = h @ Wr (partial over k halves) ----
        {
            float a0 = 0.f, a1 = 0.f, a2 = 0.f, a3 = 0.f;
            const float* hb = h_sm + zb * 256 + kh * 128;
            const float* wr0 = Wr_sm + kh * 128 * 128 + c4 * 4;
#pragma unroll 4
            for (int k = 0; k < 128; ++k) {
                float4 wv = *(const float4*)(wr0 + k * 128);
                float hv = hb[k];
                a0 += wv.x * hv;
                a1 += wv.y * hv;
                a2 += wv.z * hv;
                a3 += wv.w * hv;
            }
            *(float4*)(zpart + kh * 1024 + zb * 128 + c4 * 4) =
                make_float4(a0, a1, a2, a3);
        }
        __syncthreads();

        // ---- reduce k halves + add xW ----
        {
            const int rb = tid >> 6;
            const int l2 = (tid & 63) * 2;
            float2 p0 = *(const float2*)(zpart + rb * 128 + l2);
            float2 p1 = *(const float2*)(zpart + 1024 + rb * 128 + l2);
            const int gate = l2 >> 5, u = l2 & 31;
            float2 xw = *(const float2*)&xWd[((size_t)s * Bn + rb) * Gn +
                                             gate * Hn + U0 + u];
            z_sm[rb * 128 + l2] = p0.x + p1.x + xw.x;
            z_sm[rb * 128 + l2 + 1] = p0.y + p1.y + xw.y;
        }
        __syncthreads();

        // ---- gates / cell / a ----
        if (tid < 256) {
            const int b2 = tid >> 5, u = tid & 31;
            float zi = z_sm[b2 * 128 + u];
            float zf = z_sm[b2 * 128 + 32 + u];
            float zg = z_sm[b2 * 128 + 64 + u];
            float zo = z_sm[b2 * 128 + 96 + u];
            float ig = fsig(zi), fg = fsig(zf), gg = ftanh(zg), og = fsig(zo);
            float cold = c_sm[tid];
            float cn = fminf(3.f, fmaxf(-3.f, fg * cold + ig * gg));
            float mt = __ldg(&mask[b2 * Tn + t]);
            c_sm[tid] = (mt > 0.f) ? cn : cold;
            __stcg(&ag[b2 * Hn + U0 + u], og * ftanh(cn));
        }
        grid_barrier(++gen, tid, bx);

        // ---- phase 2: h = clip(a @ Wp) for cols P0..P0+3 ----
        {
            const float4* av4 = (const float4*)(ag + pb * Hn + half * 1024);
            float q0 = 0.f, q1 = 0.f, q2 = 0.f, q3 = 0.f;
#pragma unroll
            for (int j = 0; j < 8; ++j) {
                float4 av = __ldcg(av4 + lane + j * 32);
                const int kk = half * 1024 + (lane + j * 32) * 4;
                float4 wa = *(const float4*)&Wp_sm[kk];
                float4 wb = *(const float4*)&Wp_sm[2048 + kk];
                float4 wc = *(const float4*)&Wp_sm[4096 + kk];
                float4 wd = *(const float4*)&Wp_sm[6144 + kk];
                q0 += av.x * wa.x + av.y * wa.y + av.z * wa.z + av.w * wa.w;
                q1 += av.x * wb.x + av.y * wb.y + av.z * wb.z + av.w * wb.w;
                q2 += av.x * wc.x + av.y * wc.y + av.z * wc.z + av.w * wc.w;
                q3 += av.x * wd.x + av.y * wd.y + av.z * wd.z + av.w * wd.w;
            }
#pragma unroll
            for (int off = 16; off; off >>= 1) {
                q0 += __shfl_xor_sync(0xffffffffu, q0, off);
                q1 += __shfl_xor_sync(0xffffffffu, q1, off);
                q2 += __shfl_xor_sync(0xffffffffu, q2, off);
                q3 += __shfl_xor_sync(0xffffffffu, q3, off);
            }
            if (lane == 0)
                *(float4*)(red + (pb * 2 + half) * 4) = make_float4(q0, q1, q2, q3);
        }
        __syncthreads();
        if (tid < 32) {
            const int bb = tid >> 2, pp = tid & 3;
            float hv = red[(bb * 2) * 4 + pp] + red[(bb * 2 + 1) * 4 + pp];
            hv = fminf(3.f, fmaxf(-3.f, hv));
            float mt = __ldg(&mask[bb * Tn + t]);
            float hn = (mt > 0.f) ? hv : h_own;
            h_own = hn;
            __stcg(&hg[bb * Pn + P0 + pp], hn);
            yb[((size_t)bb * Tn + t) * Pn + P0 + pp] = hn;
        }
        grid_barrier(++gen, tid, bx);
    }

    if (bx == 0 && tid == 0)
        *((volatile unsigned*)&g_epoch) = base + 2u * Tn;
}

// ---------------------------------------------------------------------------
// Epilogue (unchanged)
// ---------------------------------------------------------------------------
__device__ __forceinline__ float layer_val(int l, int b, int t, int ch) {
    if (l == 0) return g_emb[(size_t)(b * Tn + t) * En + (ch & 255)];
    const int dd = ch >> 8;
    const size_t idx = (size_t)(b * Tn + t) * Pn + (ch & 255);
    float v = g_y0[dd][idx];
    if (l == 2) v += g_y1[dd][idx];
    return v;
}

__global__ void k_stats(const float* __restrict__ mask) {
    const int b = blockIdx.x;
    const int l = blockIdx.y;
    __shared__ float red[256];
    const int tid = threadIdx.x;

    float nm = 0.f;
    for (int t = tid; t < Tn; t += 256) nm += mask[b * Tn + t];
    red[tid] = nm;
    __syncthreads();
    for (int st = 128; st > 0; st >>= 1) {
        if (tid < st) red[tid] += red[tid + st];
        __syncthreads();
    }
    const float num = red[0];
    __syncthreads();

    float smv = 0.f;
    for (int i = tid; i < Tn * 512; i += 256) {
        int t = i >> 9, ch = i & 511;
        smv += layer_val(l, b, t, ch) * mask[b * Tn + t];
    }
    red[tid] = smv;
    __syncthreads();
    for (int st = 128; st > 0; st >>= 1) {
        if (tid < st) red[tid] += red[tid + st];
        __syncthreads();
    }
    const float mean = red[0] / num;
    __syncthreads();

    float vs = 0.f;
    for (int i = tid; i < Tn * 512; i += 256) {
        int t = i >> 9, ch = i & 511;
        float m = mask[b * Tn + t];
        float dd = (layer_val(l, b, t, ch) * m - mean) * m;
        vs += dd * dd;
    }
    red[tid] = vs;
    __syncthreads();
    for (int st = 128; st > 0; st >>= 1) {
        if (tid < st) red[tid] += red[tid + st];
        __syncthreads();
    }
    if (tid == 0) {
        g_mean[l][b] = mean;
        g_var[l][b] = red[0] / num;
    }
}

__global__ void k_final(const float* __restrict__ elmo_w, const float* __restrict__ gamma,
                        float* __restrict__ out) {
    const int i = blockIdx.x * 256 + threadIdx.x;
    const int ch = i & 511;
    const int bt = i >> 9;
    const int b = bt / Tn;
    const int t = bt - b * Tn;
    float w0 = elmo_w[0], w1 = elmo_w[1], w2 = elmo_w[2];
    float mx = fmaxf(w0, fmaxf(w1, w2));
    float e0 = expf(w0 - mx), e1 = expf(w1 - mx), e2 = expf(w2 - mx);
    float inv = 1.f / (e0 + e1 + e2);
    float gm = gamma[0];
    float r = 0.f;
    r += e0 * inv * (layer_val(0, b, t, ch) - g_mean[0][b]) / sqrtf(g_var[0][b] + 1e-12f);
    r += e1 * inv * (layer_val(1, b, t, ch) - g_mean[1][b]) / sqrtf(g_var[1][b] + 1e-12f);
    r += e2 * inv * (layer_val(2, b, t, ch) - g_mean[2][b]) / sqrtf(g_var[2][b] + 1e-12f);
    out[i] = gm * r;
}

// ---------------------------------------------------------------------------
extern "C" void kernel_launch(void* const* d_in, const int* in_sizes, int n_in,
                              void* d_out, int out_size) {
    (void)in_sizes; (void)n_in; (void)out_size;
    const int*   tokens = (const int*)d_in[0];
    const float* mask   = (const float*)d_in[1];
    const float* table  = (const float*)d_in[2];
    const float* Wk     = (const float*)d_in[3];
    const float* Wr     = (const float*)d_in[4];
    const float* bias   = (const float*)d_in[5];
    const float* Wp     = (const float*)d_in[6];
    const float* elmo_w = (const float*)d_in[7];
    const float* gamma  = (const float*)d_in[8];
    float* out = (float*)d_out;

    const int recur_smem = 185600;  // 46400 floats
    cudaFuncSetAttribute(k_recur, cudaFuncAttributeMaxDynamicSharedMemorySize,
                         recur_smem);

    k_embed<<<768, 256>>>(tokens, table);
    for (int layer = 0; layer < 2; ++layer) {
        k_xw<<<dim3(Gn / 64, (Tn * Bn) / 128, 2), 256>>>(Wk, bias, layer);
        k_recur<<<NBLK, 512, recur_smem>>>(Wr, Wp, mask, layer);
    }
    k_stats<<<dim3(8, 3), 256>>>(mask);
    k_final<<<1536, 256>>>(elmo_w, gamma, out);
}

// round 9
// speedup vs baseline: 3.4767x; 2.1772x over previous
#include <cuda_runtime.h>
#include <cuda_bf16.h>
#include <math.h>

// ---------------------------------------------------------------------------
// ELMo embeddings, fp32. Persistent recurrence + fast per-dir grid barrier.
// ---------------------------------------------------------------------------

namespace {
constexpr int Bn = 8;     // batch
constexpr int Tn = 96;    // time
constexpr int En = 256;   // embed dim
constexpr int Hn = 2048;  // hidden
constexpr int Pn = 256;   // projection
constexpr int Gn = 8192;  // 4*H
constexpr int NBLK = 128; // persistent grid (2 dirs x 64)
constexpr int DBLK = 64;  // blocks per direction
}

// scratch (device globals; allocation-free)
__device__ float g_emb[Bn * Tn * En];
__device__ float g_y0[2][Bn * Tn * Pn];
__device__ float g_y1[2][Bn * Tn * Pn];
__device__ float g_xW[2][(size_t)Tn * Bn * Gn];  // x@Wk+b, step-major
__device__ float g_h[2][Bn * Pn];
__device__ float g_a[2][Bn * Hn];
__device__ float g_mean[3][Bn];
__device__ float g_var[3][Bn];

// per-direction barrier state (monotonic; never reset -> graph-replay safe)
__device__ unsigned g_cnt[2];
__device__ unsigned g_flag[2];

// ---------------------------------------------------------------------------
__global__ void k_embed(const int* __restrict__ tok, const float* __restrict__ tab) {
    int i = blockIdx.x * 256 + threadIdx.x;  // B*T*E = 196608
    int bt = i >> 8;
    int e = i & 255;
    g_emb[i] = tab[(size_t)tok[bt] * En + e];
}

// ---------------------------------------------------------------------------
// xW GEMM: M=768 (s,b), N=8192, K=256. BM=128 BN=128 BK=16, 256 thr, 8x8
// microtile (64 FMA per 4 LDS.128).
// ---------------------------------------------------------------------------
__global__ void __launch_bounds__(256, 2)
k_xw(const float* __restrict__ Wk, const float* __restrict__ bias, int layer) {
    const int d = blockIdx.z;
    const int widx = d * 2 + layer;
    const float* __restrict__ x = (layer == 0) ? g_emb : g_y0[d];
    const float* __restrict__ W = Wk + (size_t)widx * En * Gn;
    const float* __restrict__ bi = bias + (size_t)widx * Gn;
    float* __restrict__ out = g_xW[d];
    const int n0 = blockIdx.x * 128;
    const int m0 = blockIdx.y * 128;
    const bool rev = (d == 1);
    const int tid = threadIdx.x;
    const int tx = tid & 15;   // 8 n cols at tx*8
    const int ty = tid >> 4;   // 8 m rows at ty*8

    __shared__ float As[16][132];  // [k][m]
    __shared__ float Bs[16][128];  // [k][n]

    float acc[8][8];
#pragma unroll
    for (int i = 0; i < 8; ++i)
#pragma unroll
        for (int j = 0; j < 8; ++j) acc[i][j] = 0.f;

    // A loader: row ml, 8 k at kl
    const int ml = tid >> 1;
    const int kl = (tid & 1) * 8;
    const int m = m0 + ml;
    const int sA = m >> 3, bA = m & 7;
    const int tA = rev ? (Tn - 1 - sA) : sA;
    const float* xrow = x + (size_t)(bA * Tn + tA) * En;

    // B loader: k row kb, 8 n at nb
    const int kb = tid >> 4;
    const int nb = (tid & 15) * 8;

    for (int k0 = 0; k0 < En; k0 += 16) {
        {
            float4 v0 = *(const float4*)(xrow + k0 + kl);
            float4 v1 = *(const float4*)(xrow + k0 + kl + 4);
            As[kl + 0][ml] = v0.x;
            As[kl + 1][ml] = v0.y;
            As[kl + 2][ml] = v0.z;
            As[kl + 3][ml] = v0.w;
            As[kl + 4][ml] = v1.x;
            As[kl + 5][ml] = v1.y;
            As[kl + 6][ml] = v1.z;
            As[kl + 7][ml] = v1.w;
            const float* wr = W + (size_t)(k0 + kb) * Gn + n0 + nb;
            *(float4*)(&Bs[kb][nb]) = *(const float4*)(wr);
            *(float4*)(&Bs[kb][nb + 4]) = *(const float4*)(wr + 4);
        }
        __syncthreads();
#pragma unroll
        for (int k = 0; k < 16; ++k) {
            float4 a0 = *(const float4*)(&As[k][ty * 8]);
            float4 a1 = *(const float4*)(&As[k][ty * 8 + 4]);
            float4 b0 = *(const float4*)(&Bs[k][tx * 8]);
            float4 b1 = *(const float4*)(&Bs[k][tx * 8 + 4]);
            float av[8] = {a0.x, a0.y, a0.z, a0.w, a1.x, a1.y, a1.z, a1.w};
            float bv[8] = {b0.x, b0.y, b0.z, b0.w, b1.x, b1.y, b1.z, b1.w};
#pragma unroll
            for (int i = 0; i < 8; ++i)
#pragma unroll
                for (int j = 0; j < 8; ++j) acc[i][j] += av[i] * bv[j];
        }
        __syncthreads();
    }
    float4 bva = *(const float4*)(bi + n0 + tx * 8);
    float4 bvb = *(const float4*)(bi + n0 + tx * 8 + 4);
#pragma unroll
    for (int i = 0; i < 8; ++i) {
        int mm = m0 + ty * 8 + i;
        float* op = out + (size_t)mm * Gn + n0 + tx * 8;
        *(float4*)(op) = make_float4(acc[i][0] + bva.x, acc[i][1] + bva.y,
                                     acc[i][2] + bva.z, acc[i][3] + bva.w);
        *(float4*)(op + 4) = make_float4(acc[i][4] + bvb.x, acc[i][5] + bvb.y,
                                         acc[i][6] + bvb.z, acc[i][7] + bvb.w);
    }
}

// ---------------------------------------------------------------------------
// Persistent LSTM recurrence. 128 blocks x 512 threads, 1 block/SM.
// Block bx: dir d = bx>>6, slice q = bx&63 -> units U0=q*32, proj cols P0=q*4.
// ---------------------------------------------------------------------------
__device__ __forceinline__ float fsig(float x) {
    return __fdividef(1.f, 1.f + __expf(-x));
}
__device__ __forceinline__ float ftanh(float x) {
    return __fdividef(2.f, 1.f + __expf(-2.f * x)) - 1.f;
}

// per-direction barrier: atomic arrive, thread-0 spins on one flag.
__device__ __forceinline__ void dir_barrier(int d, unsigned target, int tid) {
    __syncthreads();
    if (tid == 0) {
        __threadfence();
        unsigned old = atomicAdd(&g_cnt[d], 1u);
        if (old + 1u == target)
            *((volatile unsigned*)&g_flag[d]) = target;
        while ((int)(*((volatile unsigned*)&g_flag[d]) - target) < 0) {}
    }
    __syncthreads();
    __threadfence();
}

__global__ void __launch_bounds__(512, 1)
k_recur(const float* __restrict__ Wr, const float* __restrict__ Wp,
        const float* __restrict__ mask, int layer) {
    extern __shared__ float sm[];
    float* Wr_sm = sm;            // [256][128] (k*128+lc), lc = gate*32+u
    float* Wp_sm = sm + 32768;    // [4][2048]  (p*2048+k)
    float* hT    = sm + 40960;    // [256][8]   (p*8+b)  transposed h
    float* zpart = sm + 43008;    // [8][8][128] (kc*1024 + b*128 + lc)
    float* z_sm  = sm + 51200;    // [8][128]
    float* c_sm  = sm + 52224;    // [8][32]
    float* red   = sm + 52480;    // [8][2][4]
    // total 52544 floats = 210176 B

    const int tid = threadIdx.x;
    const int bx = blockIdx.x;
    const int d = bx >> 6;
    const int q = bx & 63;
    const int U0 = q * 32;
    const int P0 = q * 4;
    const int widx = d * 2 + layer;

    // ---- preload weights ----
    {
        const float* Wg = Wr + (size_t)widx * Pn * Gn;
        for (int i = tid; i < 256 * 128; i += 512) {
            int k = i >> 7, lc = i & 127;
            int gate = lc >> 5, u = lc & 31;
            Wr_sm[i] = __ldg(&Wg[(size_t)k * Gn + gate * Hn + U0 + u]);
        }
        const float* Wpg = Wp + (size_t)widx * Hn * Pn;
        for (int k = tid; k < Hn; k += 512) {
            float4 v = __ldg((const float4*)&Wpg[(size_t)k * Pn + P0]);
            Wp_sm[k] = v.x;
            Wp_sm[2048 + k] = v.y;
            Wp_sm[4096 + k] = v.z;
            Wp_sm[6144 + k] = v.w;
        }
    }
    if (tid < 256) c_sm[tid] = 0.f;

    const unsigned base = *((volatile unsigned*)&g_flag[d]);
    unsigned target = base;
    float h_own = 0.f;
    float* __restrict__ yb = (layer == 0) ? g_y0[d] : g_y1[d];
    float* __restrict__ hg = g_h[d];
    float* __restrict__ ag = g_a[d];
    const float* __restrict__ xWd = g_xW[d];
    __syncthreads();

    // role indices
    const int kc = tid >> 5;          // phase1 (tid<256): k-chunk
    const int cg = tid & 31;          // phase1: 4-col group
    const int rb = tid >> 6;          // reduce: batch
    const int l2 = (tid & 63) * 2;    // reduce: 2 cols
    const int rgate = l2 >> 5, ru = l2 & 31;
    const int w = tid >> 5;           // phase2 warp
    const int lane = tid & 31;
    const int pb = w >> 1;            // phase2 batch
    const int half = w & 1;           // phase2 k half

    for (int s = 0; s < Tn; ++s) {
        const int t = d ? (Tn - 1 - s) : s;

        // prefetch xW for the reduce stage (hide DRAM latency behind phase1)
        float2 xwv = __ldcg((const float2*)&xWd[((size_t)s * Bn + rb) * Gn +
                                                rgate * Hn + U0 + ru]);

        // ---- stage h transposed: hT[p*8+b] = h[b*256+p] ----
        if (s == 0) {
            for (int i = tid; i < Bn * Pn; i += 512) hT[i] = 0.f;
        } else {
#pragma unroll
            for (int i = tid; i < Bn * Pn; i += 512) {
                int b = i >> 8, p = i & 255;
                hT[p * 8 + b] = __ldcg(&hg[i]);
            }
        }
        __syncthreads();

        // ---- phase 1: z partials = h @ Wr (8 k-chunks of 32) ----
        if (tid < 256) {
            float acc[8][4];
#pragma unroll
            for (int b = 0; b < 8; ++b)
                acc[b][0] = acc[b][1] = acc[b][2] = acc[b][3] = 0.f;
            const float* wr0 = Wr_sm + cg * 4;
            const int ke = kc * 32 + 32;
#pragma unroll 4
            for (int k = kc * 32; k < ke; ++k) {
                float4 wv = *(const float4*)(wr0 + k * 128);
                float h8[8];
                *(float4*)(h8) = *(const float4*)(hT + k * 8);
                *(float4*)(h8 + 4) = *(const float4*)(hT + k * 8 + 4);
#pragma unroll
                for (int b = 0; b < 8; ++b) {
                    acc[b][0] += wv.x * h8[b];
                    acc[b][1] += wv.y * h8[b];
                    acc[b][2] += wv.z * h8[b];
                    acc[b][3] += wv.w * h8[b];
                }
            }
#pragma unroll
            for (int b = 0; b < 8; ++b)
                *(float4*)(zpart + kc * 1024 + b * 128 + cg * 4) =
                    make_float4(acc[b][0], acc[b][1], acc[b][2], acc[b][3]);
        }
        __syncthreads();

        // ---- reduce k-chunks + add xW ----
        {
            float z0 = xwv.x, z1 = xwv.y;
#pragma unroll
            for (int kk = 0; kk < 8; ++kk) {
                float2 p = *(const float2*)(zpart + kk * 1024 + rb * 128 + l2);
                z0 += p.x;
                z1 += p.y;
            }
            *(float2*)(z_sm + rb * 128 + l2) = make_float2(z0, z1);
        }
        __syncthreads();

        // ---- gates / cell / a ----
        if (tid < 256) {
            const int b2 = tid >> 5, u = tid & 31;
            float zi = z_sm[b2 * 128 + u];
            float zf = z_sm[b2 * 128 + 32 + u];
            float zg = z_sm[b2 * 128 + 64 + u];
            float zo = z_sm[b2 * 128 + 96 + u];
            float ig = fsig(zi), fg = fsig(zf), gg = ftanh(zg), og = fsig(zo);
            float cold = c_sm[tid];
            float cn = fminf(3.f, fmaxf(-3.f, fg * cold + ig * gg));
            float mt = __ldg(&mask[b2 * Tn + t]);
            c_sm[tid] = (mt > 0.f) ? cn : cold;
            __stcg(&ag[b2 * Hn + U0 + u], og * ftanh(cn));
        }
        target += DBLK;
        dir_barrier(d, target, tid);

        // ---- phase 2: h cols P0..P0+3 = clip(a @ Wp) ----
        {
            const float4* av4 = (const float4*)(ag + pb * Hn + half * 1024);
            float q0 = 0.f, q1 = 0.f, q2 = 0.f, q3 = 0.f;
#pragma unroll
            for (int j = 0; j < 8; ++j) {
                float4 av = __ldcg(av4 + lane + j * 32);
                const int kk = half * 1024 + (lane + j * 32) * 4;
                float4 wa = *(const float4*)&Wp_sm[kk];
                float4 wb = *(const float4*)&Wp_sm[2048 + kk];
                float4 wc = *(const float4*)&Wp_sm[4096 + kk];
                float4 wd = *(const float4*)&Wp_sm[6144 + kk];
                q0 += av.x * wa.x + av.y * wa.y + av.z * wa.z + av.w * wa.w;
                q1 += av.x * wb.x + av.y * wb.y + av.z * wb.z + av.w * wb.w;
                q2 += av.x * wc.x + av.y * wc.y + av.z * wc.z + av.w * wc.w;
                q3 += av.x * wd.x + av.y * wd.y + av.z * wd.z + av.w * wd.w;
            }
#pragma unroll
            for (int off = 16; off; off >>= 1) {
                q0 += __shfl_xor_sync(0xffffffffu, q0, off);
                q1 += __shfl_xor_sync(0xffffffffu, q1, off);
                q2 += __shfl_xor_sync(0xffffffffu, q2, off);
                q3 += __shfl_xor_sync(0xffffffffu, q3, off);
            }
            if (lane == 0)
                *(float4*)(red + (pb * 2 + half) * 4) = make_float4(q0, q1, q2, q3);
        }
        __syncthreads();
        if (tid < 32) {
            const int bb = tid >> 2, pp = tid & 3;
            float hv = red[(bb * 2) * 4 + pp] + red[(bb * 2 + 1) * 4 + pp];
            hv = fminf(3.f, fmaxf(-3.f, hv));
            float mt = __ldg(&mask[bb * Tn + t]);
            float hn = (mt > 0.f) ? hv : h_own;
            h_own = hn;
            __stcg(&hg[bb * Pn + P0 + pp], hn);
            yb[((size_t)bb * Tn + t) * Pn + P0 + pp] = hn;
        }
        target += DBLK;
        dir_barrier(d, target, tid);
    }
}

// ---------------------------------------------------------------------------
// Epilogue (unchanged)
// ---------------------------------------------------------------------------
__device__ __forceinline__ float layer_val(int l, int b, int t, int ch) {
    if (l == 0) return g_emb[(size_t)(b * Tn + t) * En + (ch & 255)];
    const int dd = ch >> 8;
    const size_t idx = (size_t)(b * Tn + t) * Pn + (ch & 255);
    float v = g_y0[dd][idx];
    if (l == 2) v += g_y1[dd][idx];
    return v;
}

__global__ void k_stats(const float* __restrict__ mask) {
    const int b = blockIdx.x;
    const int l = blockIdx.y;
    __shared__ float red[256];
    const int tid = threadIdx.x;

    float nm = 0.f;
    for (int t = tid; t < Tn; t += 256) nm += mask[b * Tn + t];
    red[tid] = nm;
    __syncthreads();
    for (int st = 128; st > 0; st >>= 1) {
        if (tid < st) red[tid] += red[tid + st];
        __syncthreads();
    }
    const float num = red[0];
    __syncthreads();

    float smv = 0.f;
    for (int i = tid; i < Tn * 512; i += 256) {
        int t = i >> 9, ch = i & 511;
        smv += layer_val(l, b, t, ch) * mask[b * Tn + t];
    }
    red[tid] = smv;
    __syncthreads();
    for (int st = 128; st > 0; st >>= 1) {
        if (tid < st) red[tid] += red[tid + st];
        __syncthreads();
    }
    const float mean = red[0] / num;
    __syncthreads();

    float vs = 0.f;
    for (int i = tid; i < Tn * 512; i += 256) {
        int t = i >> 9, ch = i & 511;
        float m = mask[b * Tn + t];
        float dd = (layer_val(l, b, t, ch) * m - mean) * m;
        vs += dd * dd;
    }
    red[tid] = vs;
    __syncthreads();
    for (int st = 128; st > 0; st >>= 1) {
        if (tid < st) red[tid] += red[tid + st];
        __syncthreads();
    }
    if (tid == 0) {
        g_mean[l][b] = mean;
        g_var[l][b] = red[0] / num;
    }
}

__global__ void k_final(const float* __restrict__ elmo_w, const float* __restrict__ gamma,
                        float* __restrict__ out) {
    const int i = blockIdx.x * 256 + threadIdx.x;
    const int ch = i & 511;
    const int bt = i >> 9;
    const int b = bt / Tn;
    const int t = bt - b * Tn;
    float w0 = elmo_w[0], w1 = elmo_w[1], w2 = elmo_w[2];
    float mx = fmaxf(w0, fmaxf(w1, w2));
    float e0 = expf(w0 - mx), e1 = expf(w1 - mx), e2 = expf(w2 - mx);
    float inv = 1.f / (e0 + e1 + e2);
    float gm = gamma[0];
    float r = 0.f;
    r += e0 * inv * (layer_val(0, b, t, ch) - g_mean[0][b]) / sqrtf(g_var[0][b] + 1e-12f);
    r += e1 * inv * (layer_val(1, b, t, ch) - g_mean[1][b]) / sqrtf(g_var[1][b] + 1e-12f);
    r += e2 * inv * (layer_val(2, b, t, ch) - g_mean[2][b]) / sqrtf(g_var[2][b] + 1e-12f);
    out[i] = gm * r;
}

// ---------------------------------------------------------------------------
extern "C" void kernel_launch(void* const* d_in, const int* in_sizes, int n_in,
                              void* d_out, int out_size) {
    (void)in_sizes; (void)n_in; (void)out_size;
    const int*   tokens = (const int*)d_in[0];
    const float* mask   = (const float*)d_in[1];
    const float* table  = (const float*)d_in[2];
    const float* Wk     = (const float*)d_in[3];
    const float* Wr     = (const float*)d_in[4];
    const float* bias   = (const float*)d_in[5];
    const float* Wp     = (const float*)d_in[6];
    const float* elmo_w = (const float*)d_in[7];
    const float* gamma  = (const float*)d_in[8];
    float* out = (float*)d_out;

    const int recur_smem = 210176;  // 52544 floats
    cudaFuncSetAttribute(k_recur, cudaFuncAttributeMaxDynamicSharedMemorySize,
                         recur_smem);

    k_embed<<<768, 256>>>(tokens, table);
    for (int layer = 0; layer < 2; ++layer) {
        k_xw<<<dim3(Gn / 128, (Tn * Bn) / 128, 2), 256>>>(Wk, bias, layer);
        k_recur<<<NBLK, 512, recur_smem>>>(Wr, Wp, mask, layer);
    }
    k_stats<<<dim3(8, 3), 256>>>(mask);
    k_final<<<1536, 256>>>(elmo_w, gamma, out);
}